// round 6
// baseline (speedup 1.0000x reference)
#include <cuda_runtime.h>
#include <math.h>

#define Bn 512
#define Ln 64
#define En 256
#define Hn 256
#define CD 64
#define HCn 320     // H + CDIM
#define KX 512      // E + H
#define G4 1024     // 4*H
#define NEGV -1000000000.0f
#define NBLK 444    // 3 blocks/SM on 148 SMs (<=152 on GB300: still all-resident)

// ---------------- scratch (static device globals; allocation-free) ----------
__device__ float g_eg[Bn*Ln*Hn];     // e_g  [b][l][h]
__device__ float g_ep[Bn*Ln*Hn];     // e_p  [b][l][h]
__device__ float g_xh[Bn*KX];        // [x | h] LSTM input
__device__ float g_hc[Bn*HCn];       // [h | courier]
__device__ float g_gates[Bn*G4];
__device__ float g_c[Bn*Hn];
__device__ float g_gl[Bn*Hn];
__device__ float g_qg[Bn*Hn];
__device__ float g_gl2[Bn*Hn];
__device__ float g_qp[Bn*Hn];
__device__ float g_Wcat[G4*KX];      // [W_ih | W_hh]
__device__ float g_bcat[G4];         // b_ih + b_hh
__device__ unsigned char g_mask[Bn*Ln];
__device__ unsigned int g_sync;      // grid barrier counter (reset each launch)

__device__ __forceinline__ float sigf(float x) { return 1.0f/(1.0f+expf(-x)); }

// ---------------- software grid barrier (all NBLK blocks resident) ----------
__device__ __forceinline__ void gbar(unsigned int &cnt) {
    __syncthreads();
    cnt += gridDim.x;
    if (threadIdx.x == 0) {
        __threadfence();                         // release
        atomicAdd(&g_sync, 1u);
        while (*(volatile unsigned int*)&g_sync < cnt) { }
        __threadfence();                         // acquire
    }
    __syncthreads();
}

// ---------------- gates GEMM: 64x64 tiles, 4x4/thread, 128 jobs -------------
// C[m][n] = sum_k A[m][k]*W[n][k] + bias[n],  M=512 N=1024 K=512
__device__ void gemm_gates(const float* __restrict__ A, const float* __restrict__ W,
                           const float* __restrict__ bias, float* __restrict__ C,
                           char* sm)
{
    float (*As)[16][64] = (float (*)[16][64])sm;            // 8 KB
    float (*Ws)[16][64] = (float (*)[16][64])(sm + 8192);   // 8 KB
    const int tid = threadIdx.x;
    const int job = blockIdx.x;
    if (job < 128) {
        const int m0 = (job & 7) << 6;          // 8 m-tiles
        const int n0 = (job >> 3) << 6;         // 16 n-tiles
        const int lr = tid >> 2;                // 0..63 load row
        const int lc = (tid & 3) << 2;          // k offset
        const int ty = tid >> 4;                // 0..15 -> rows 4ty..4ty+3
        const int tx = tid & 15;                // cols 4tx..4tx+3

        const float* Ap = A + (size_t)(m0 + lr) * KX + lc;
        const float* Wp = W + (size_t)(n0 + lr) * KX + lc;
        float4 ra = *(const float4*)Ap;
        float4 rw = *(const float4*)Wp;
        float acc[4][4] = {};
        __syncthreads();                        // smem reuse across phases
        int buf = 0;
        for (int k0 = 0; k0 < KX; k0 += 16) {
            As[buf][lc+0][lr]=ra.x; As[buf][lc+1][lr]=ra.y;
            As[buf][lc+2][lr]=ra.z; As[buf][lc+3][lr]=ra.w;
            Ws[buf][lc+0][lr]=rw.x; Ws[buf][lc+1][lr]=rw.y;
            Ws[buf][lc+2][lr]=rw.z; Ws[buf][lc+3][lr]=rw.w;
            __syncthreads();
            if (k0 + 16 < KX) {
                ra = *(const float4*)(Ap + k0 + 16);
                rw = *(const float4*)(Wp + k0 + 16);
            }
            #pragma unroll
            for (int kk = 0; kk < 16; kk++) {
                float4 a = *(const float4*)&As[buf][kk][ty<<2];
                float4 w = *(const float4*)&Ws[buf][kk][tx<<2];
                float ar[4] = {a.x,a.y,a.z,a.w};
                float wr[4] = {w.x,w.y,w.z,w.w};
                #pragma unroll
                for (int i = 0; i < 4; i++)
                    #pragma unroll
                    for (int j = 0; j < 4; j++)
                        acc[i][j] = fmaf(ar[i], wr[j], acc[i][j]);
            }
            buf ^= 1;
        }
        const int nc = n0 + (tx << 2);
        const float4 bv = *(const float4*)(bias + nc);
        #pragma unroll
        for (int i = 0; i < 4; i++) {
            float* Cr = C + (size_t)(m0 + (ty<<2) + i) * G4 + nc;
            *(float4*)Cr = make_float4(acc[i][0]+bv.x, acc[i][1]+bv.y,
                                       acc[i][2]+bv.z, acc[i][3]+bv.w);
        }
    }
}

// ---------------- small GEMM: 8x64 tiles, 256 jobs (M=512, N=256) -----------
template<int K>
__device__ void gemm_small(const float* __restrict__ A, const float* __restrict__ W,
                           const float* __restrict__ bias, float* __restrict__ C,
                           char* sm)
{
    float (*sA)[16][8]  = (float (*)[16][8])sm;             // 1 KB
    float (*sW)[16][64] = (float (*)[16][64])(sm + 1024);   // 8 KB
    const int tid = threadIdx.x;
    const int job = blockIdx.x;
    if (job < 256) {
        const int m0 = (job & 63) << 3;         // 64 m-tiles
        const int n0 = (job >> 6) << 6;         // 4 n-tiles
        const int tr = tid >> 5;                // 0..7 output row
        const int tc = tid & 31;                // cols 2tc, 2tc+1
        const bool aAct = tid < 32;
        const int am = tid >> 2;                // 0..7
        const int ak = (tid & 3) << 2;
        const int wn = tid >> 2;                // 0..63
        const int wk = (tid & 3) << 2;

        const float* Arow = A + (size_t)(m0 + am) * K + ak;
        const float* Wrow = W + (size_t)(n0 + wn) * K + wk;
        float4 ra, rw;
        if (aAct) ra = *(const float4*)Arow;
        rw = *(const float4*)Wrow;
        float acc0 = 0.f, acc1 = 0.f;
        __syncthreads();
        int buf = 0;
        for (int k0 = 0; k0 < K; k0 += 16) {
            if (aAct) {
                sA[buf][ak+0][am]=ra.x; sA[buf][ak+1][am]=ra.y;
                sA[buf][ak+2][am]=ra.z; sA[buf][ak+3][am]=ra.w;
            }
            sW[buf][wk+0][wn]=rw.x; sW[buf][wk+1][wn]=rw.y;
            sW[buf][wk+2][wn]=rw.z; sW[buf][wk+3][wn]=rw.w;
            __syncthreads();
            if (k0 + 16 < K) {
                if (aAct) ra = *(const float4*)(Arow + k0 + 16);
                rw = *(const float4*)(Wrow + k0 + 16);
            }
            #pragma unroll
            for (int kk = 0; kk < 16; kk++) {
                const float a = sA[buf][kk][tr];
                const float2 w = *(const float2*)&sW[buf][kk][tc<<1];
                acc0 = fmaf(a, w.x, acc0);
                acc1 = fmaf(a, w.y, acc1);
            }
            buf ^= 1;
        }
        const int nc = n0 + (tc << 1);
        *(float2*)(C + (size_t)(m0+tr)*Hn + nc) =
            make_float2(acc0 + bias[nc], acc1 + bias[nc+1]);
    }
}

// ---------------- one-time e_g/e_p GEMM (unchanged) -------------------------
template<int REMAP>
__global__ __launch_bounds__(256) void gemm_bias(
    const float* __restrict__ A, const float* __restrict__ W,
    const float* __restrict__ bias, float* __restrict__ C,
    int M, int N, int K)
{
    __shared__ float As[16][64];
    __shared__ float Ws[16][64];
    const int m0 = blockIdx.y * 64, n0 = blockIdx.x * 64;
    const int tid = threadIdx.x;
    const int lr = tid >> 2;
    const int lc = (tid & 3) * 4;
    const int ty = tid >> 4, tx = tid & 15;

    float acc[4][4] = {};
    int mrow = m0 + lr;
    int arow = REMAP ? ((mrow & 63) * Bn + (mrow >> 6)) : mrow;
    const float* Ap = A + (size_t)arow * K + lc;
    const float* Wp = W + (size_t)(n0 + lr) * K + lc;

    for (int k0 = 0; k0 < K; k0 += 16) {
        float4 av = *(const float4*)(Ap + k0);
        float4 wv = *(const float4*)(Wp + k0);
        As[lc+0][lr]=av.x; As[lc+1][lr]=av.y; As[lc+2][lr]=av.z; As[lc+3][lr]=av.w;
        Ws[lc+0][lr]=wv.x; Ws[lc+1][lr]=wv.y; Ws[lc+2][lr]=wv.z; Ws[lc+3][lr]=wv.w;
        __syncthreads();
        #pragma unroll
        for (int kk = 0; kk < 16; kk++) {
            float4 a = *(const float4*)&As[kk][ty*4];
            float4 w = *(const float4*)&Ws[kk][tx*4];
            float ar[4] = {a.x,a.y,a.z,a.w};
            float wr[4] = {w.x,w.y,w.z,w.w};
            #pragma unroll
            for (int i = 0; i < 4; i++)
                #pragma unroll
                for (int j = 0; j < 4; j++)
                    acc[i][j] += ar[i]*wr[j];
        }
        __syncthreads();
    }
    #pragma unroll
    for (int i = 0; i < 4; i++) {
        int m = m0 + ty*4 + i;
        float* Crow = C + (size_t)m*N + n0 + tx*4;
        #pragma unroll
        for (int j = 0; j < 4; j++)
            Crow[j] = acc[i][j] + bias[n0 + tx*4 + j];
    }
}

// ---------------- one-time setup ----------------
__global__ void setup_kernel(
    const float* __restrict__ dec, const float* __restrict__ h0,
    const float* __restrict__ c0, const float* __restrict__ courier,
    const unsigned char* __restrict__ im,
    const float* __restrict__ W_ih, const float* __restrict__ W_hh,
    const float* __restrict__ b_ih, const float* __restrict__ b_hh)
{
    int i = blockIdx.x * blockDim.x + threadIdx.x;
    if (i == 0) g_sync = 0;                       // reset grid barrier each launch
    if (i < G4*KX) {
        int n = i / KX, k = i % KX;
        g_Wcat[i] = (k < En) ? W_ih[n*En + k] : W_hh[n*Hn + (k - En)];
    }
    if (i < G4)    g_bcat[i] = b_ih[i] + b_hh[i];
    if (i < Bn*KX) {
        int b = i / KX, j = i % KX;
        g_xh[i] = (j < En) ? dec[b*En + j] : h0[b*Hn + (j - En)];
    }
    if (i < Bn*Hn) g_c[i] = c0[i];
    if (i < Bn*CD) {
        int b = i / CD, j = i % CD;
        g_hc[b*HCn + Hn + j] = courier[i];
    }
    if (i < Bn*Ln) g_mask[i] = im[i];
}

// ---------------- the persistent decoder kernel -----------------------------
__global__ __launch_bounds__(256, 3) void persist_kernel(
    const float* __restrict__ emb,
    const float* __restrict__ Wm,   const float* __restrict__ bm,
    const float* __restrict__ Wq_g, const float* __restrict__ bq_g,
    const float* __restrict__ Wq_p, const float* __restrict__ bq_p,
    const float* __restrict__ v_g,  const float* __restrict__ v_p,
    float* __restrict__ out)
{
    extern __shared__ char smc[];                // 16 KB GEMM buffers
    __shared__ float wv[64];
    __shared__ float s_m, s_ls;
    __shared__ int   s_sel;

    const int t = threadIdx.x;
    const int warp = t >> 5, lane = t & 31;
    const int nthr = gridDim.x * blockDim.x;
    unsigned int barcnt = 0;

    for (int step = 0; step < Ln; step++) {
        // ---- P1: gates = [x|h] @ Wcat^T + bcat ----
        gemm_gates(g_xh, g_Wcat, g_bcat, g_gates, smc);
        gbar(barcnt);

        // ---- P2: LSTM pointwise ----
        for (int i = blockIdx.x * blockDim.x + t; i < Bn*Hn; i += nthr) {
            int b = i >> 8, j = i & 255;
            const float* g = g_gates + b*G4;
            float iv = sigf(g[j]);
            float fv = sigf(g[j + 256]);
            float gv = tanhf(g[j + 512]);
            float ov = sigf(g[j + 768]);
            float c = fv * g_c[i] + iv * gv;
            float h = ov * tanhf(c);
            g_c[i]              = c;
            g_xh[b*KX + En + j] = h;
            g_hc[b*HCn + j]     = h;
        }
        gbar(barcnt);

        // ---- P3: gl = [h|courier] @ Wm^T + bm  (K=320) ----
        gemm_small<HCn>(g_hc, Wm, bm, g_gl, smc);
        gbar(barcnt);

        // ---- P4: qg = gl @ Wq_g^T + bq_g ----
        gemm_small<Hn>(g_gl, Wq_g, bq_g, g_qg, smc);
        gbar(barcnt);

        // ---- P5: attention g (scores + softmax + weighted sum) ----
        for (int b = blockIdx.x; b < Bn; b += gridDim.x) {
            __syncthreads();                      // protect wv reuse
            const float* E = g_eg + (size_t)b * Ln * Hn;
            float qr[8], vr[8];
            #pragma unroll
            for (int j = 0; j < 8; j++) {
                qr[j] = g_qg[b*Hn + lane + 32*j];
                vr[j] = v_g[lane + 32*j];
            }
            #pragma unroll
            for (int l0 = 0; l0 < 64; l0 += 8) {
                int l = l0 + warp;
                const float* row = E + l * 256;
                float acc = 0.f;
                #pragma unroll
                for (int j = 0; j < 8; j++)
                    acc += vr[j] * tanhf(qr[j] + row[lane + 32*j]);
                #pragma unroll
                for (int o = 16; o; o >>= 1) acc += __shfl_xor_sync(0xffffffffu, acc, o);
                if (lane == 0) wv[l] = g_mask[b*Ln + l] ? NEGV : acc;
            }
            __syncthreads();

            if (warp == 0) {
                float a = wv[lane], c = wv[lane + 32];
                float m = fmaxf(a, c);
                #pragma unroll
                for (int o = 16; o; o >>= 1) m = fmaxf(m, __shfl_xor_sync(0xffffffffu, m, o));
                float ea = expf(a - m), ec = expf(c - m);
                float s = ea + ec;
                #pragma unroll
                for (int o = 16; o; o >>= 1) s += __shfl_xor_sync(0xffffffffu, s, o);
                wv[lane]      = ea / s;
                wv[lane + 32] = ec / s;
            }
            __syncthreads();

            float acc = 0.f;
            #pragma unroll 8
            for (int l = 0; l < 64; l++) acc += E[l*256 + t] * wv[l];
            g_gl2[b*Hn + t] = acc;
        }
        gbar(barcnt);

        // ---- P6: qp = gl2 @ Wq_p^T + bq_p ----
        gemm_small<Hn>(g_gl2, Wq_p, bq_p, g_qp, smc);
        gbar(barcnt);

        // ---- P7: attention p (log-softmax + argmax + mask + gather) ----
        for (int b = blockIdx.x; b < Bn; b += gridDim.x) {
            __syncthreads();                      // protect wv reuse
            const float* E = g_ep + (size_t)b * Ln * Hn;
            float qr[8], vr[8];
            #pragma unroll
            for (int j = 0; j < 8; j++) {
                qr[j] = g_qp[b*Hn + lane + 32*j];
                vr[j] = v_p[lane + 32*j];
            }
            #pragma unroll
            for (int l0 = 0; l0 < 64; l0 += 8) {
                int l = l0 + warp;
                const float* row = E + l * 256;
                float acc = 0.f;
                #pragma unroll
                for (int j = 0; j < 8; j++)
                    acc += vr[j] * tanhf(qr[j] + row[lane + 32*j]);
                #pragma unroll
                for (int o = 16; o; o >>= 1) acc += __shfl_xor_sync(0xffffffffu, acc, o);
                if (lane == 0) wv[l] = g_mask[b*Ln + l] ? NEGV : (10.0f * tanhf(acc));
            }
            __syncthreads();

            if (warp == 0) {
                float a = wv[lane], c = wv[lane + 32];
                float m = fmaxf(a, c);
                #pragma unroll
                for (int o = 16; o; o >>= 1) m = fmaxf(m, __shfl_xor_sync(0xffffffffu, m, o));
                float s = expf(a - m) + expf(c - m);
                #pragma unroll
                for (int o = 16; o; o >>= 1) s += __shfl_xor_sync(0xffffffffu, s, o);
                float bv = a; int bi = lane;
                if (c > bv) { bv = c; bi = lane + 32; }
                #pragma unroll
                for (int o = 16; o; o >>= 1) {
                    float ov = __shfl_xor_sync(0xffffffffu, bv, o);
                    int   oi = __shfl_xor_sync(0xffffffffu, bi, o);
                    if (ov > bv || (ov == bv && oi < bi)) { bv = ov; bi = oi; }
                }
                if (lane == 0) {
                    s_m = m; s_ls = logf(s); s_sel = bi;
                    unsigned char* mk = g_mask + b*Ln;
                    mk[bi] = 1;
                    int cnt = 0;
                    #pragma unroll
                    for (int l = 0; l < Ln; l++) cnt += mk[l];
                    if (cnt == Ln) mk[Ln - 1] = 0;
                    out[(size_t)(Bn*Ln*Ln) + (size_t)b*Ln + step] = (float)bi;
                }
            }
            __syncthreads();

            if (t < Ln)
                out[(size_t)b*Ln*Ln + (size_t)step*Ln + t] = wv[t] - s_m - s_ls;

            int sel = s_sel;
            g_xh[b*KX + t] = emb[((size_t)sel*Bn + b)*En + t];
        }
        gbar(barcnt);
    }
}

// ---------------- host ----------------
extern "C" void kernel_launch(void* const* d_in, const int* in_sizes, int n_in,
                              void* d_out, int out_size)
{
    const float* dec     = (const float*)d_in[0];
    const float* emb     = (const float*)d_in[1];
    const float* h0      = (const float*)d_in[2];
    const float* c0      = (const float*)d_in[3];
    const float* ctx     = (const float*)d_in[4];
    const float* courier = (const float*)d_in[5];
    const unsigned char* initm = (const unsigned char*)d_in[6];
    const float* W_ih = (const float*)d_in[7];
    const float* W_hh = (const float*)d_in[8];
    const float* b_ih = (const float*)d_in[9];
    const float* b_hh = (const float*)d_in[10];
    const float* Wm   = (const float*)d_in[11];
    const float* bm   = (const float*)d_in[12];
    const float* Wq_p = (const float*)d_in[13];
    const float* bq_p = (const float*)d_in[14];
    const float* Wr_p = (const float*)d_in[15];
    const float* br_p = (const float*)d_in[16];
    const float* v_p  = (const float*)d_in[17];
    const float* Wq_g = (const float*)d_in[18];
    const float* bq_g = (const float*)d_in[19];
    const float* Wr_g = (const float*)d_in[20];
    const float* br_g = (const float*)d_in[21];
    const float* v_g  = (const float*)d_in[22];
    float* out = (float*)d_out;

    cudaFuncSetAttribute(persist_kernel, cudaFuncAttributeMaxDynamicSharedMemorySize, 16384);

    float *eg, *ep;
    cudaGetSymbolAddress((void**)&eg, g_eg);
    cudaGetSymbolAddress((void**)&ep, g_ep);

    setup_kernel<<<1024, 512>>>(dec, h0, c0, courier, initm, W_ih, W_hh, b_ih, b_hh);

    // e_g / e_p = context @ Wr^T + br, stored [b][l][h]
    gemm_bias<1><<<dim3(Hn/64, (Bn*Ln)/64), 256>>>(ctx, Wr_g, br_g, eg, Bn*Ln, Hn, Hn);
    gemm_bias<1><<<dim3(Hn/64, (Bn*Ln)/64), 256>>>(ctx, Wr_p, br_p, ep, Bn*Ln, Hn, Hn);

    persist_kernel<<<NBLK, 256, 16384>>>(emb, Wm, bm, Wq_g, bq_g, Wq_p, bq_p,
                                         v_g, v_p, out);
}